// round 11
// baseline (speedup 1.0000x reference)
#include <cuda_runtime.h>
#include <math.h>
#include <stdint.h>

#define NNODES 50000
#define TT 8
#define HH 128
#define COUT 32
#define EDGES 800000
#define MROWS 400000

// ======================= scratch (device globals) ============================
__device__ int   g_is64;
__device__ int   g_src[EDGES];
__device__ int   g_dst[EDGES];
__device__ int   g_cnt[NNODES];
__device__ int   g_off[NNODES];
__device__ int   g_cur[NNODES];
__device__ int   g_adj[EDGES];
__device__ float g_AX  [(size_t)MROWS*64];   // [m=(n*8+t), 64] = [agg/deg | x]
__device__ float g_Wcat[HH*64];              // [128, 64]  = [Wl | Wr]
__device__ float g_Wihh[384*256];            // [384, 256] = [W_ih | W_hh]
__device__ float g_Wh  [96*HH];              // [96, 128]  = [W_rec ; W_c1]
__device__ float g_bh  [96];

// ======================= helpers =============================================
__device__ __forceinline__ float tf32_rna(float v) {
    uint32_t r;
    asm("cvt.rna.tf32.f32 %0, %1;" : "=r"(r) : "f"(v));
    return __uint_as_float(r);
}
#define MMA_TF32(C, Af, Bf) \
    asm volatile( \
        "mma.sync.aligned.m16n8k8.row.col.f32.tf32.tf32.f32 " \
        "{%0,%1,%2,%3}, {%4,%5,%6,%7}, {%8,%9}, {%0,%1,%2,%3};" \
        : "+f"((C)[0]), "+f"((C)[1]), "+f"((C)[2]), "+f"((C)[3]) \
        : "r"((Af)[0]), "r"((Af)[1]), "r"((Af)[2]), "r"((Af)[3]), \
          "r"((Bf)[0]), "r"((Bf)[1]))
#define CP_ASYNC16(dst, src, sz) \
    asm volatile("cp.async.ca.shared.global [%0], [%1], 16, %2;" \
                 :: "r"(dst), "l"(src), "r"(sz))
#define CP_COMMIT() asm volatile("cp.async.commit_group;" ::: "memory")
#define CP_WAIT1()  asm volatile("cp.async.wait_group 1;" ::: "memory")
#define CP_WAIT0()  asm volatile("cp.async.wait_group 0;" ::: "memory")
__device__ __forceinline__ float sigmoidf_(float v) { return 1.f / (1.f + expf(-v)); }

// split helper: hi/lo tf32 pair
#define SPLIT2(bfh, bfl, b0, b1) do { \
    float _h0 = tf32_rna(b0), _h1 = tf32_rna(b1); \
    bfh[0] = __float_as_uint(_h0); bfl[0] = __float_as_uint((b0) - _h0); \
    bfh[1] = __float_as_uint(_h1); bfl[1] = __float_as_uint((b1) - _h1); \
} while (0)

// ======================= edge prep ===========================================
__global__ void detect_kernel(const void* ei) {
    const unsigned long long* p = (const unsigned long long*)ei;
    int is64 = 1;
    for (int i = 0; i < 1024; i++)
        if ((p[i] >> 32) != 0ull) { is64 = 0; break; }
    g_is64 = is64;
}
__global__ void zero_kernel() {
    int idx = blockIdx.x * blockDim.x + threadIdx.x;
    int stride = gridDim.x * blockDim.x;
    for (int i = idx; i < NNODES; i += stride) g_cnt[i] = 0;
}
__global__ void convcount_kernel(const void* ei) {
    int e = blockIdx.x * blockDim.x + threadIdx.x;
    if (e >= EDGES) return;
    int s, d;
    if (g_is64) {
        const long long* p = (const long long*)ei;
        s = (int)p[e]; d = (int)p[EDGES + e];
    } else {
        const int* p = (const int*)ei;
        s = p[e]; d = p[EDGES + e];
    }
    s = min(max(s, 0), NNODES - 1);
    d = min(max(d, 0), NNODES - 1);
    g_src[e] = s;
    g_dst[e] = d;
    atomicAdd(&g_cnt[d], 1);
}
__global__ void scan_kernel() {
    __shared__ int partial[1024];
    const int CH = (NNODES + 1023) / 1024;
    int t = threadIdx.x;
    int begin = t * CH;
    int end   = min(begin + CH, NNODES);
    int s = 0;
    for (int i = begin; i < end; i++) s += g_cnt[i];
    partial[t] = s;
    __syncthreads();
    #pragma unroll
    for (int d = 1; d < 1024; d <<= 1) {
        int v = (t >= d) ? partial[t - d] : 0;
        __syncthreads();
        partial[t] += v;
        __syncthreads();
    }
    int off = partial[t] - s;
    for (int i = begin; i < end; i++) {
        g_off[i] = off;
        g_cur[i] = off;
        off += g_cnt[i];
    }
}
__global__ void fill_kernel() {
    int e = blockIdx.x * blockDim.x + threadIdx.x;
    if (e >= EDGES) return;
    int pos = atomicAdd(&g_cur[g_dst[e]], 1);
    g_adj[pos] = g_src[e];
}
__global__ void __launch_bounds__(256) gather_kernel(const float* __restrict__ x) {
    int n   = blockIdx.x;
    int idx = threadIdx.x;
    int beg = g_off[n];
    int cnt = g_cnt[n];
    float s = 0.f;
    for (int p = beg; p < beg + cnt; p++) {
        int src = g_adj[p];
        s += x[(size_t)src * 256 + idx];
    }
    float dg = fmaxf((float)cnt, 1.f);
    int t = idx >> 5, c = idx & 31;
    size_t m = (size_t)n * 8 + t;
    g_AX[m * 64 + c]      = s / dg;
    g_AX[m * 64 + 32 + c] = x[(size_t)n * 256 + idx];
}
__global__ void wcat_kernel(const float* __restrict__ Wl, const float* __restrict__ Wr) {
    int idx = blockIdx.x * blockDim.x + threadIdx.x;
    if (idx >= HH*64) return;
    int j = idx >> 6, c = idx & 63;
    g_Wcat[idx] = (c < 32) ? Wl[j*32 + c] : Wr[j*32 + (c-32)];
}
__global__ void wihh_kernel(const float* __restrict__ W_ih, const float* __restrict__ W_hh) {
    int idx = blockIdx.x * blockDim.x + threadIdx.x;
    if (idx >= 384*256) return;
    int r = idx >> 8, c = idx & 255;
    g_Wihh[idx] = (c < 128) ? W_ih[r*128 + c] : W_hh[r*128 + (c - 128)];
}
__global__ void headcat_kernel(const float* __restrict__ W_rec, const float* __restrict__ b_rec,
                               const float* __restrict__ W_c1,  const float* __restrict__ b_c1) {
    int idx = blockIdx.x * blockDim.x + threadIdx.x;
    if (idx < 96*HH) {
        int r = idx >> 7, k = idx & 127;
        g_Wh[idx] = (r < 32) ? W_rec[r*128 + k] : W_c1[(r-32)*128 + k];
    }
    if (idx < 96) g_bh[idx] = (idx < 32) ? b_rec[idx] : b_c1[idx - 32];
}

// ======================= mega kernel =========================================
// One CTA = 64 nodes, 512 thr (16 warps, wm=warp>>2 rows, wn=warp&3 cols).
// Per step t: A) SP=relu(AX_t@Wcat^T+bl) -> ACAT[:,0:128]
//             B) gates = [SP|H]@Wihh^T (K=256; H-chunk n-gate -> accn)
//                GRU in regs -> hn -> ACAT[:,128:256]
//             C) head = hn@Wh^T -> recon/c1 -> cls
#define SROW 36
#define BSTG (384*SROW)                /* 13824 words per stage */
#define ACOFF (2*BSTG)                 /* 27648 */
#define ACST 260                       /* [SP|H] row stride (mod 32 = 4) */
#define AXOFF (ACOFF + 64*ACST)        /* 44288 */
#define AXST 68
#define MEGA_SMEM ((AXOFF + 64*AXST)*4)   /* 194560 B */

__global__ void __launch_bounds__(512, 1) mega_kernel(
    const float* __restrict__ bl,  const float* __restrict__ b_ih,
    const float* __restrict__ b_hh,
    const float* __restrict__ w2,  const float* __restrict__ b2,
    float* __restrict__ recon, float* __restrict__ clsOut)
{
    extern __shared__ float smem[];
    uint32_t smem_b;
    asm("{ .reg .u64 t; cvta.to.shared.u64 t, %1; cvt.u32.u64 %0, t; }"
        : "=r"(smem_b) : "l"(smem));

    const int tid  = threadIdx.x;
    const int lane = tid & 31;
    const int w    = tid >> 5;
    const int gid  = lane >> 2;
    const int tig  = lane & 3;
    const int wm   = w >> 2;
    const int wn   = w & 3;
    const int bm   = blockIdx.x * 64;

    float* ACAT = smem + ACOFF;
    float* AXS  = smem + AXOFF;
    const int r0 = wm*16 + gid;           // warp A-row base (rows r0, r0+8)

    for (int t = 0; t < TT; t++) {
        // ================= phase A: SP =================
        auto issueA = [&](int kc) {
            const uint32_t sb = smem_b + (uint32_t)((kc & 1) * BSTG) * 4u;
            if (kc == 0) {
                #pragma unroll
                for (int h = 0; h < 2; h++) {     // AX_t: 64 rows x 16 segs
                    int i = tid + h*512;
                    int row = i >> 4, seg = i & 15;
                    int node = bm + row;
                    const float* src = g_AX + (size_t)(min(node, NNODES-1)*8 + t)*64 + seg*4;
                    CP_ASYNC16(smem_b + (uint32_t)(AXOFF + row*AXST + seg*4)*4u,
                               src, (node < NNODES) ? 16 : 0);
                }
            }
            #pragma unroll
            for (int h = 0; h < 2; h++) {         // Wcat chunk: 128 rows x 8 segs
                int i = tid + h*512;
                int row = i >> 3, seg = i & 7;
                CP_ASYNC16(sb + (uint32_t)(row*SROW + seg*4)*4u,
                           g_Wcat + (size_t)row*64 + kc*32 + seg*4, 16);
            }
            CP_COMMIT();
        };

        float accsp[4][4] = {};
        issueA(0);
        for (int kc = 0; kc < 2; kc++) {
            if (kc + 1 < 2) { issueA(kc + 1); CP_WAIT1(); } else { CP_WAIT0(); }
            __syncthreads();
            const float* Bf = smem + (kc & 1) * BSTG;
            #pragma unroll
            for (int k8 = 0; k8 < 4; k8++) {
                const int ka = kc*32 + k8*8;
                uint32_t afh[4], afl[4];
                {
                    float a0 = AXS[ r0     *AXST + ka + tig    ];
                    float a1 = AXS[(r0 + 8)*AXST + ka + tig    ];
                    float a2 = AXS[ r0     *AXST + ka + tig + 4];
                    float a3 = AXS[(r0 + 8)*AXST + ka + tig + 4];
                    SPLIT2((afh+0), (afl+0), a0, a1);
                    SPLIT2((afh+2), (afl+2), a2, a3);
                }
                #pragma unroll
                for (int nt = 0; nt < 4; nt++) {
                    int cb = wn*32 + nt*8 + gid;
                    float b0 = Bf[cb*SROW + k8*8 + tig    ];
                    float b1 = Bf[cb*SROW + k8*8 + tig + 4];
                    uint32_t bfh[2], bfl[2];
                    SPLIT2(bfh, bfl, b0, b1);
                    MMA_TF32(accsp[nt], afh, bfh);
                    MMA_TF32(accsp[nt], afh, bfl);
                    MMA_TF32(accsp[nt], afl, bfh);
                }
            }
            __syncthreads();
        }
        #pragma unroll
        for (int nt = 0; nt < 4; nt++) {
            int col = wn*32 + nt*8 + 2*tig;
            #pragma unroll
            for (int half = 0; half < 2; half++) {
                int lrow = r0 + half*8;
                ACAT[lrow*ACST + col]     = fmaxf(accsp[nt][half*2+0] + bl[col],   0.f);
                ACAT[lrow*ACST + col + 1] = fmaxf(accsp[nt][half*2+1] + bl[col+1], 0.f);
            }
        }
        __syncthreads();

        // ================= phase B: gates + GRU =================
        const int KCB = (t == 0) ? 4 : 8;
        auto issueB = [&](int kc) {
            const uint32_t sb = smem_b + (uint32_t)((kc & 1) * BSTG) * 4u;
            #pragma unroll
            for (int h = 0; h < 6; h++) {         // 384 rows x 8 segs
                int i = tid + h*512;
                int row = i >> 3, seg = i & 7;
                CP_ASYNC16(sb + (uint32_t)(row*SROW + seg*4)*4u,
                           g_Wihh + (size_t)row*256 + kc*32 + seg*4, 16);
            }
            CP_COMMIT();
        };

        float acc[3][4][4] = {};
        float accn[4][4]   = {};
        issueB(0);
        for (int kc = 0; kc < KCB; kc++) {
            if (kc + 1 < KCB) { issueB(kc + 1); CP_WAIT1(); } else { CP_WAIT0(); }
            __syncthreads();
            const float* Bf = smem + (kc & 1) * BSTG;
            if (kc < 4) {
                // SP chunks: all gates -> acc
                #pragma unroll
                for (int k8 = 0; k8 < 4; k8++) {
                    const int ka = kc*32 + k8*8;
                    uint32_t afh[4], afl[4];
                    {
                        float a0 = ACAT[ r0     *ACST + ka + tig    ];
                        float a1 = ACAT[(r0 + 8)*ACST + ka + tig    ];
                        float a2 = ACAT[ r0     *ACST + ka + tig + 4];
                        float a3 = ACAT[(r0 + 8)*ACST + ka + tig + 4];
                        SPLIT2((afh+0), (afl+0), a0, a1);
                        SPLIT2((afh+2), (afl+2), a2, a3);
                    }
                    #pragma unroll
                    for (int g = 0; g < 3; g++) {
                        #pragma unroll
                        for (int nt = 0; nt < 4; nt++) {
                            int cb = g*128 + wn*32 + nt*8 + gid;
                            float b0 = Bf[cb*SROW + k8*8 + tig    ];
                            float b1 = Bf[cb*SROW + k8*8 + tig + 4];
                            uint32_t bfh[2], bfl[2];
                            SPLIT2(bfh, bfl, b0, b1);
                            MMA_TF32(acc[g][nt], afh, bfh);
                            MMA_TF32(acc[g][nt], afh, bfl);
                            MMA_TF32(acc[g][nt], afl, bfh);
                        }
                    }
                }
            } else {
                // H chunks: r,z -> acc; n -> accn
                #pragma unroll
                for (int k8 = 0; k8 < 4; k8++) {
                    const int ka = kc*32 + k8*8;
                    uint32_t afh[4], afl[4];
                    {
                        float a0 = ACAT[ r0     *ACST + ka + tig    ];
                        float a1 = ACAT[(r0 + 8)*ACST + ka + tig    ];
                        float a2 = ACAT[ r0     *ACST + ka + tig + 4];
                        float a3 = ACAT[(r0 + 8)*ACST + ka + tig + 4];
                        SPLIT2((afh+0), (afl+0), a0, a1);
                        SPLIT2((afh+2), (afl+2), a2, a3);
                    }
                    #pragma unroll
                    for (int g = 0; g < 2; g++) {
                        #pragma unroll
                        for (int nt = 0; nt < 4; nt++) {
                            int cb = g*128 + wn*32 + nt*8 + gid;
                            float b0 = Bf[cb*SROW + k8*8 + tig    ];
                            float b1 = Bf[cb*SROW + k8*8 + tig + 4];
                            uint32_t bfh[2], bfl[2];
                            SPLIT2(bfh, bfl, b0, b1);
                            MMA_TF32(acc[g][nt], afh, bfh);
                            MMA_TF32(acc[g][nt], afh, bfl);
                            MMA_TF32(acc[g][nt], afl, bfh);
                        }
                    }
                    #pragma unroll
                    for (int nt = 0; nt < 4; nt++) {
                        int cb = 2*128 + wn*32 + nt*8 + gid;
                        float b0 = Bf[cb*SROW + k8*8 + tig    ];
                        float b1 = Bf[cb*SROW + k8*8 + tig + 4];
                        uint32_t bfh[2], bfl[2];
                        SPLIT2(bfh, bfl, b0, b1);
                        MMA_TF32(accn[nt], afh, bfh);
                        MMA_TF32(accn[nt], afh, bfl);
                        MMA_TF32(accn[nt], afl, bfh);
                    }
                }
            }
            __syncthreads();
        }

        // GRU in registers -> hn -> ACAT[:,128:256]
        #pragma unroll
        for (int nt = 0; nt < 4; nt++) {
            int col = wn*32 + nt*8 + 2*tig;
            float bir0 = b_ih[col],       bir1 = b_ih[col+1];
            float biz0 = b_ih[128+col],   biz1 = b_ih[128+col+1];
            float bin0 = b_ih[256+col],   bin1 = b_ih[256+col+1];
            float bhr0 = b_hh[col],       bhr1 = b_hh[col+1];
            float bhz0 = b_hh[128+col],   bhz1 = b_hh[128+col+1];
            float bhn0 = b_hh[256+col],   bhn1 = b_hh[256+col+1];
            #pragma unroll
            for (int half = 0; half < 2; half++) {
                int lrow = r0 + half*8;
                float h0 = (t == 0) ? 0.f : ACAT[lrow*ACST + 128 + col];
                float h1 = (t == 0) ? 0.f : ACAT[lrow*ACST + 128 + col + 1];
                float rr0 = sigmoidf_(acc[0][nt][half*2+0] + bir0 + bhr0);
                float rr1 = sigmoidf_(acc[0][nt][half*2+1] + bir1 + bhr1);
                float zz0 = sigmoidf_(acc[1][nt][half*2+0] + biz0 + bhz0);
                float zz1 = sigmoidf_(acc[1][nt][half*2+1] + biz1 + bhz1);
                float nn0 = tanhf(acc[2][nt][half*2+0] + bin0 + rr0*(accn[nt][half*2+0] + bhn0));
                float nn1 = tanhf(acc[2][nt][half*2+1] + bin1 + rr1*(accn[nt][half*2+1] + bhn1));
                ACAT[lrow*ACST + 128 + col]     = (1.f - zz0)*nn0 + zz0*h0;
                ACAT[lrow*ACST + 128 + col + 1] = (1.f - zz1)*nn1 + zz1*h1;
            }
        }
        __syncthreads();

        // ================= phase C: heads =================
        auto issueC = [&](int kc) {
            const uint32_t sb = smem_b + (uint32_t)((kc & 1) * BSTG) * 4u;
            #pragma unroll
            for (int h = 0; h < 2; h++) {         // 96 rows x 8 segs = 768
                int i = tid + h*512;
                if (i < 768) {
                    int row = i >> 3, seg = i & 7;
                    CP_ASYNC16(sb + (uint32_t)(row*SROW + seg*4)*4u,
                               g_Wh + (size_t)row*128 + kc*32 + seg*4, 16);
                }
            }
            CP_COMMIT();
        };

        float acch[3][4] = {};
        issueC(0);
        for (int kc = 0; kc < 4; kc++) {
            if (kc + 1 < 4) { issueC(kc + 1); CP_WAIT1(); } else { CP_WAIT0(); }
            __syncthreads();
            const float* Bf = smem + (kc & 1) * BSTG;
            #pragma unroll
            for (int k8 = 0; k8 < 4; k8++) {
                const int ka = 128 + kc*32 + k8*8;     // hn region
                uint32_t afh[4], afl[4];
                {
                    float a0 = ACAT[ r0     *ACST + ka + tig    ];
                    float a1 = ACAT[(r0 + 8)*ACST + ka + tig    ];
                    float a2 = ACAT[ r0     *ACST + ka + tig + 4];
                    float a3 = ACAT[(r0 + 8)*ACST + ka + tig + 4];
                    SPLIT2((afh+0), (afl+0), a0, a1);
                    SPLIT2((afh+2), (afl+2), a2, a3);
                }
                #pragma unroll
                for (int nt = 0; nt < 3; nt++) {
                    int cb = wn*24 + nt*8 + gid;
                    float b0 = Bf[cb*SROW + k8*8 + tig    ];
                    float b1 = Bf[cb*SROW + k8*8 + tig + 4];
                    uint32_t bfh[2], bfl[2];
                    SPLIT2(bfh, bfl, b0, b1);
                    MMA_TF32(acch[nt], afh, bfh);
                    MMA_TF32(acch[nt], afh, bfl);
                    MMA_TF32(acch[nt], afl, bfh);
                }
            }
            __syncthreads();
        }
        // head epilogue: recon + c1(relu) stage (c1 into AXS region)
        #pragma unroll
        for (int nt = 0; nt < 3; nt++) {
            int col = wn*24 + nt*8 + 2*tig;
            #pragma unroll
            for (int half = 0; half < 2; half++) {
                int lrow = r0 + half*8;
                int node = bm + lrow;
                float ox = acch[nt][half*2+0] + g_bh[col];
                float oy = acch[nt][half*2+1] + g_bh[col+1];
                if (col < 32) {
                    if (node < NNODES) {
                        float2 o = make_float2(ox, oy);
                        *(float2*)(recon + (size_t)(node*8 + t)*32 + col) = o;
                    }
                } else {
                    AXS[lrow*AXST + col - 32]     = fmaxf(ox, 0.f);
                    AXS[lrow*AXST + col - 32 + 1] = fmaxf(oy, 0.f);
                }
            }
        }
        __syncthreads();
        // cls: 16 warps x 4 rows
        #pragma unroll
        for (int rr = 0; rr < 4; rr++) {
            int lrow = w*4 + rr;
            float s = AXS[lrow*AXST + lane]      * w2[lane]
                    + AXS[lrow*AXST + 32 + lane] * w2[32 + lane];
            #pragma unroll
            for (int o = 16; o; o >>= 1) s += __shfl_xor_sync(0xffffffffu, s, o);
            int node = bm + lrow;
            if (lane == 0 && node < NNODES)
                clsOut[(size_t)node*8 + t] = sigmoidf_(s + b2[0]);
        }
        __syncthreads();
    }
}

// ======================= launch ==============================================
extern "C" void kernel_launch(void* const* d_in, const int* in_sizes, int n_in,
                              void* d_out, int out_size)
{
    const float* x     = (const float*)d_in[0];
    const void*  ei    = d_in[1];
    const float* Wl    = (const float*)d_in[2];
    const float* bl    = (const float*)d_in[3];
    const float* Wr    = (const float*)d_in[4];
    const float* W_ih  = (const float*)d_in[5];
    const float* b_ih  = (const float*)d_in[6];
    const float* W_hh  = (const float*)d_in[7];
    const float* b_hh  = (const float*)d_in[8];
    const float* W_rec = (const float*)d_in[9];
    const float* b_rec = (const float*)d_in[10];
    const float* W_c1  = (const float*)d_in[11];
    const float* b_c1  = (const float*)d_in[12];
    const float* W_c2  = (const float*)d_in[13];
    const float* b_c2  = (const float*)d_in[14];

    float* out      = (float*)d_out;
    float* outRecon = out;
    float* outCls   = out + (size_t)MROWS * COUT;

    cudaFuncSetAttribute(mega_kernel, cudaFuncAttributeMaxDynamicSharedMemorySize, MEGA_SMEM);

    // graph + weight prep
    detect_kernel<<<1, 1>>>(ei);
    zero_kernel<<<256, 256>>>();
    convcount_kernel<<<(EDGES + 255)/256, 256>>>(ei);
    wcat_kernel<<<(HH*64 + 255)/256, 256>>>(Wl, Wr);
    wihh_kernel<<<(384*256 + 255)/256, 256>>>(W_ih, W_hh);
    headcat_kernel<<<(96*HH + 255)/256, 256>>>(W_rec, b_rec, W_c1, b_c1);
    scan_kernel<<<1, 1024>>>();
    fill_kernel<<<(EDGES + 255)/256, 256>>>();
    gather_kernel<<<NNODES, 256>>>(x);

    // the whole model: SP+GX+8xGRU+heads, one persistent launch
    mega_kernel<<<(NNODES + 63)/64, 512, MEGA_SMEM>>>(
        bl, b_ih, b_hh, W_c2, b_c2, outRecon, outCls);
}